// round 1
// baseline (speedup 1.0000x reference)
#include <cuda_runtime.h>
#include <math.h>

// ---------------------------------------------------------------------------
// EGNN edge message:
//   radial = |x[s]-x[d]|^2
//   h1 = silu( radial*W1[0,:] + (hh@W1[1:65])[s] + (hh@W1[65:129])[d] + b1 )
//   h2 = silu( h1@W2 + b2 )            (= edge_feature)
//   h3 = silu( h2@W3 + b3 )
//   sc = tanh( h3@W4 )
//   trans = (x[s]-x[d]) / (sqrt(radial)+eps) * sc
// Output layout: [ radial (E) | trans (3E) | edge_feature (64E) ]
//
// Strategy:
//   Kernel 1: precompute P[n] = [ hh[n]@W1a + b1 | hh[n]@W1b ]  (50K x 128)
//             -> halves per-edge FLOPs of the first layer.
//   Kernel 2: 2 edges/thread, f32x2 packed FMAs, W2/W3 uniform-broadcast from
//             smem, h vectors in padded smem rows, staged coalesced writeback.
// ---------------------------------------------------------------------------

#define N_MAX_NODES 50048
__device__ float g_P[(size_t)N_MAX_NODES * 128];

__device__ __forceinline__ float siluf(float v) {
    return __fdividef(v, 1.0f + __expf(-v));
}
__device__ __forceinline__ unsigned long long pk2(float x) {
    unsigned long long r; asm("mov.b64 %0, {%1, %1};" : "=l"(r) : "f"(x)); return r;
}
__device__ __forceinline__ unsigned long long f2fma(unsigned long long a,
                                                    unsigned long long b,
                                                    unsigned long long c) {
    unsigned long long d;
    asm("fma.rn.f32x2 %0, %1, %2, %3;" : "=l"(d) : "l"(a), "l"(b), "l"(c));
    return d;
}
__device__ __forceinline__ void unpk(unsigned long long v, float& lo, float& hi) {
    asm("mov.b64 {%0, %1}, %2;" : "=f"(lo), "=f"(hi) : "l"(v));
}

// ---------------- Kernel 1: per-node projection precompute -----------------
__global__ void __launch_bounds__(256) precompute_P_kernel(
    const float* __restrict__ hh, const float* __restrict__ W1,
    const float* __restrict__ b1, int n_nodes, int nodes_per_block)
{
    __shared__ float W1s[129 * 64];
    __shared__ float b1s[64];
    int tid = threadIdx.x;
    for (int i = tid; i < 129 * 64; i += 256) W1s[i] = W1[i];
    if (tid < 64) b1s[tid] = b1[tid];
    __syncthreads();

    int lane = tid & 31, warp = tid >> 5;
    for (int nn = warp; nn < nodes_per_block; nn += 8) {
        int n = blockIdx.x * nodes_per_block + nn;
        if (n >= n_nodes) return;
        float hlo = hh[(size_t)n * 64 + lane];
        float hhi = hh[(size_t)n * 64 + 32 + lane];
        float a0 = b1s[lane], a1 = b1s[lane + 32];   // Pa (src part) + b1 folded
        float c0 = 0.f, c1 = 0.f;                    // Pb (dst part)
        #pragma unroll
        for (int k = 0; k < 64; k++) {
            float hk = __shfl_sync(0xffffffffu, (k < 32) ? hlo : hhi, k & 31);
            a0 = fmaf(hk, W1s[(1 + k) * 64 + lane],        a0);
            a1 = fmaf(hk, W1s[(1 + k) * 64 + 32 + lane],   a1);
            c0 = fmaf(hk, W1s[(65 + k) * 64 + lane],       c0);
            c1 = fmaf(hk, W1s[(65 + k) * 64 + 32 + lane],  c1);
        }
        float* Pr = g_P + (size_t)n * 128;
        Pr[lane] = a0; Pr[lane + 32] = a1;
        Pr[64 + lane] = c0; Pr[96 + lane] = c1;
    }
}

// ------------------------- 64x64 GEMM (2 edges) -----------------------------
// h rows: padded stride 68 floats (17 float4) -> conflict-free own-row LDS.128.
// W rows: uniform across warp -> broadcast LDS.128 (1 wavefront).
__device__ __forceinline__ void gemm64(
    const float* Ws, const float4* hrow0, const float4* hrow1,
    unsigned long long (&A0)[32], unsigned long long (&A1)[32])
{
    const ulonglong2* Wu = (const ulonglong2*)Ws;
    #pragma unroll 1
    for (int k4 = 0; k4 < 16; k4++) {
        float4 f0 = hrow0[k4];
        float4 f1 = hrow1[k4];
        #pragma unroll
        for (int kk = 0; kk < 4; kk++) {
            float s0 = (kk == 0) ? f0.x : (kk == 1) ? f0.y : (kk == 2) ? f0.z : f0.w;
            float s1 = (kk == 0) ? f1.x : (kk == 1) ? f1.y : (kk == 2) ? f1.z : f1.w;
            unsigned long long p0 = pk2(s0), p1 = pk2(s1);
            const ulonglong2* wr = Wu + (k4 * 4 + kk) * 16;
            #pragma unroll
            for (int j = 0; j < 16; j++) {
                ulonglong2 w = wr[j];
                A0[2 * j]     = f2fma(p0, w.x, A0[2 * j]);
                A0[2 * j + 1] = f2fma(p0, w.y, A0[2 * j + 1]);
                A1[2 * j]     = f2fma(p1, w.x, A1[2 * j]);
                A1[2 * j + 1] = f2fma(p1, w.y, A1[2 * j + 1]);
            }
        }
    }
}

// ---------------------------- Kernel 2: edges -------------------------------
// smem floats: W2s 4096 | W3s 4096 | w1r0 64 | b2 64 | b3 64 | W4 64 | h 256*68
// total 25856 floats = 103424 B. 2 blocks/SM.
__global__ void __launch_bounds__(128, 2) edge_kernel(
    const float* __restrict__ x,
    const int* __restrict__ src, const int* __restrict__ dst,
    const float* __restrict__ W1,
    const float* __restrict__ W2, const float* __restrict__ b2,
    const float* __restrict__ W3, const float* __restrict__ b3,
    const float* __restrict__ W4,
    float* __restrict__ out, int E)
{
    extern __shared__ float sm[];
    float* W2s  = sm;
    float* W3s  = sm + 4096;
    float* w1r0 = sm + 8192;
    float* b2s  = sm + 8256;
    float* b3s  = sm + 8320;
    float* W4s  = sm + 8384;
    float* h1s  = sm + 8448;          // 256 rows x 68 floats

    int tid = threadIdx.x;
    for (int i = tid; i < 4096; i += 128) { W2s[i] = W2[i]; W3s[i] = W3[i]; }
    if (tid < 64) { w1r0[tid] = W1[tid]; b2s[tid] = b2[tid]; b3s[tid] = b3[tid]; W4s[tid] = W4[tid]; }
    __syncthreads();

    int base = blockIdx.x * 256;
    int e0 = base + tid, e1 = base + 128 + tid;
    bool v0 = e0 < E, v1 = e1 < E;
    int s0 = v0 ? src[e0] : 0, d0 = v0 ? dst[e0] : 0;
    int s1 = v1 ? src[e1] : 0, d1 = v1 ? dst[e1] : 0;

    float cx0 = x[s0 * 3 + 0] - x[d0 * 3 + 0];
    float cy0 = x[s0 * 3 + 1] - x[d0 * 3 + 1];
    float cz0 = x[s0 * 3 + 2] - x[d0 * 3 + 2];
    float r0 = cx0 * cx0 + cy0 * cy0 + cz0 * cz0;
    float cx1 = x[s1 * 3 + 0] - x[d1 * 3 + 0];
    float cy1 = x[s1 * 3 + 1] - x[d1 * 3 + 1];
    float cz1 = x[s1 * 3 + 2] - x[d1 * 3 + 2];
    float r1 = cx1 * cx1 + cy1 * cy1 + cz1 * cz1;

    if (v0) out[e0] = r0;             // radial
    if (v1) out[e1] = r1;

    // ---- layer 1: h1 = silu(r*W1row0 + Pa[s] + Pb[d]) -> smem row ----
    {
        const float4* pa0 = (const float4*)(g_P + (size_t)s0 * 128);
        const float4* pb0 = (const float4*)(g_P + (size_t)d0 * 128 + 64);
        const float4* pa1 = (const float4*)(g_P + (size_t)s1 * 128);
        const float4* pb1 = (const float4*)(g_P + (size_t)d1 * 128 + 64);
        const float4* w1q = (const float4*)w1r0;
        float4* hw0 = (float4*)(h1s + tid * 68);
        float4* hw1 = (float4*)(h1s + (128 + tid) * 68);
        #pragma unroll
        for (int q = 0; q < 16; q++) {
            float4 w = w1q[q];
            float4 a = pa0[q], b = pb0[q];
            float4 h;
            h.x = siluf(fmaf(r0, w.x, a.x + b.x));
            h.y = siluf(fmaf(r0, w.y, a.y + b.y));
            h.z = siluf(fmaf(r0, w.z, a.z + b.z));
            h.w = siluf(fmaf(r0, w.w, a.w + b.w));
            hw0[q] = h;
            a = pa1[q]; b = pb1[q];
            h.x = siluf(fmaf(r1, w.x, a.x + b.x));
            h.y = siluf(fmaf(r1, w.y, a.y + b.y));
            h.z = siluf(fmaf(r1, w.z, a.z + b.z));
            h.w = siluf(fmaf(r1, w.w, a.w + b.w));
            hw1[q] = h;
        }
    }

    const float4* hr0 = (const float4*)(h1s + tid * 68);
    const float4* hr1 = (const float4*)(h1s + (128 + tid) * 68);

    // ---- layer 2: h2 = silu(h1@W2 + b2) = edge_feature ----
    unsigned long long A0[32], A1[32];
    {
        const unsigned long long* b2u = (const unsigned long long*)b2s;
        #pragma unroll
        for (int p = 0; p < 32; p++) { A0[p] = b2u[p]; A1[p] = b2u[p]; }
    }
    gemm64(W2s, hr0, hr1, A0, A1);
    {
        float4* hw0 = (float4*)(h1s + tid * 68);
        float4* hw1 = (float4*)(h1s + (128 + tid) * 68);
        #pragma unroll
        for (int p2 = 0; p2 < 16; p2++) {
            float a, b, c, d; float4 v;
            unpk(A0[2 * p2], a, b); unpk(A0[2 * p2 + 1], c, d);
            v.x = siluf(a); v.y = siluf(b); v.z = siluf(c); v.w = siluf(d);
            hw0[p2] = v;
            unpk(A1[2 * p2], a, b); unpk(A1[2 * p2 + 1], c, d);
            v.x = siluf(a); v.y = siluf(b); v.z = siluf(c); v.w = siluf(d);
            hw1[p2] = v;
        }
    }

    // ---- layer 3: h3 = silu(h2@W3 + b3) ----
    {
        const unsigned long long* b3u = (const unsigned long long*)b3s;
        #pragma unroll
        for (int p = 0; p < 32; p++) { A0[p] = b3u[p]; A1[p] = b3u[p]; }
    }
    gemm64(W3s, hr0, hr1, A0, A1);

    // ---- layer 4: sc = tanh(h3 . W4); trans = cd * sc / (sqrt(r)+eps) ----
    float dot0 = 0.f, dot1 = 0.f;
    #pragma unroll
    for (int p = 0; p < 32; p++) {
        float lo, hi;
        unpk(A0[p], lo, hi);
        dot0 = fmaf(siluf(lo), W4s[2 * p], fmaf(siluf(hi), W4s[2 * p + 1], dot0));
        unpk(A1[p], lo, hi);
        dot1 = fmaf(siluf(lo), W4s[2 * p], fmaf(siluf(hi), W4s[2 * p + 1], dot1));
    }
    float m0 = __fdividef(tanhf(dot0), sqrtf(r0) + 1e-8f);
    float m1 = __fdividef(tanhf(dot1), sqrtf(r1) + 1e-8f);
    float* outT = out + E;
    if (v0) {
        outT[3 * e0 + 0] = cx0 * m0;
        outT[3 * e0 + 1] = cy0 * m0;
        outT[3 * e0 + 2] = cz0 * m0;
    }
    if (v1) {
        outT[3 * e1 + 0] = cx1 * m1;
        outT[3 * e1 + 1] = cy1 * m1;
        outT[3 * e1 + 2] = cz1 * m1;
    }

    // ---- staged coalesced writeback of edge_feature (h2 kept in smem) ----
    __syncthreads();
    int nvalid = E - base; if (nvalid > 256) nvalid = 256;
    float4* outF = (float4*)(out + (size_t)4 * E);
    const float4* h4 = (const float4*)h1s;
    for (int idx = tid; idx < nvalid * 16; idx += 128) {
        int edge = idx >> 4, q = idx & 15;
        outF[(size_t)(base + edge) * 16 + q] = h4[edge * 17 + q];
    }
}

extern "C" void kernel_launch(void* const* d_in, const int* in_sizes, int n_in,
                              void* d_out, int out_size) {
    const float* x  = (const float*)d_in[0];
    const float* hh = (const float*)d_in[1];
    const int* src  = (const int*)d_in[2];
    const int* dst  = (const int*)d_in[3];
    const float* W1 = (const float*)d_in[4];
    const float* b1 = (const float*)d_in[5];
    const float* W2 = (const float*)d_in[6];
    const float* b2 = (const float*)d_in[7];
    const float* W3 = (const float*)d_in[8];
    const float* b3 = (const float*)d_in[9];
    const float* W4 = (const float*)d_in[10];
    int N = in_sizes[0] / 3;
    int E = in_sizes[2];
    float* out = (float*)d_out;

    cudaFuncSetAttribute(edge_kernel,
                         cudaFuncAttributeMaxDynamicSharedMemorySize, 103424);

    const int npb = 80;
    int pblocks = (N + npb - 1) / npb;
    precompute_P_kernel<<<pblocks, 256>>>(hh, W1, b1, N, npb);

    int eblocks = (E + 255) / 256;
    edge_kernel<<<eblocks, 128, 103424>>>(x, src, dst, W1, W2, b2, W3, b3, W4,
                                          out, E);
    (void)n_in; (void)out_size;
}

// round 3
// speedup vs baseline: 1.6470x; 1.6470x over previous
#include <cuda_runtime.h>
#include <cuda_bf16.h>
#include <math.h>
#include <stdint.h>

// ---------------------------------------------------------------------------
// EGNN edge message via warp-level HMMA (mma.sync bf16, hi/lo split x3).
//   Kernel 1: P[n] = [ hh[n]@W1a + b1 | hh[n]@W1b ]
//   Kernel 2 (per 128-edge block, 4 warps x 32 rows):
//     h1 = silu(Pa[s]+Pb[d]+r*W1row0)               (fp32, per-thread)
//     h2 = silu(h1@W2+b2)  via mma.sync m16n8k16    (edge_feature, fp32 out)
//     h3 = silu(h2@W3+b3)  via mma.sync
//     sc = tanh(h3.W4); trans = cd*sc/(sqrt(r)+eps)
// Output: [ radial (E) | trans (3E) | edge_feature (64E) ]
// ---------------------------------------------------------------------------

#define N_MAX_NODES 50048
__device__ float g_P[(size_t)N_MAX_NODES * 128];

__device__ __forceinline__ float siluf(float v) {
    return __fdividef(v, 1.0f + __expf(-v));
}

// ---------------- Kernel 1: per-node projection precompute -----------------
__global__ void __launch_bounds__(256) precompute_P_kernel(
    const float* __restrict__ hh, const float* __restrict__ W1,
    const float* __restrict__ b1, int n_nodes, int nodes_per_block)
{
    __shared__ float W1s[129 * 64];
    __shared__ float b1s[64];
    int tid = threadIdx.x;
    for (int i = tid; i < 129 * 64; i += 256) W1s[i] = W1[i];
    if (tid < 64) b1s[tid] = b1[tid];
    __syncthreads();

    int lane = tid & 31, warp = tid >> 5;
    for (int nn = warp; nn < nodes_per_block; nn += 8) {
        int n = blockIdx.x * nodes_per_block + nn;
        if (n >= n_nodes) return;
        float hlo = hh[(size_t)n * 64 + lane];
        float hhi = hh[(size_t)n * 64 + 32 + lane];
        float a0 = b1s[lane], a1 = b1s[lane + 32];
        float c0 = 0.f, c1 = 0.f;
        #pragma unroll
        for (int k = 0; k < 64; k++) {
            float hk = __shfl_sync(0xffffffffu, (k < 32) ? hlo : hhi, k & 31);
            a0 = fmaf(hk, W1s[(1 + k) * 64 + lane],        a0);
            a1 = fmaf(hk, W1s[(1 + k) * 64 + 32 + lane],   a1);
            c0 = fmaf(hk, W1s[(65 + k) * 64 + lane],       c0);
            c1 = fmaf(hk, W1s[(65 + k) * 64 + 32 + lane],  c1);
        }
        float* Pr = g_P + (size_t)n * 128;
        Pr[lane] = a0; Pr[lane + 32] = a1;
        Pr[64 + lane] = c0; Pr[96 + lane] = c1;
    }
}

// ------------------------------ helpers ------------------------------------
__device__ __forceinline__ void split_pair(float a, float b,
                                           uint32_t& hi, uint32_t& lo) {
    __nv_bfloat162 h2 = __floats2bfloat162_rn(a, b);
    float ra = a - __bfloat162float(h2.x);
    float rb = b - __bfloat162float(h2.y);
    __nv_bfloat162 l2 = __floats2bfloat162_rn(ra, rb);
    hi = *reinterpret_cast<uint32_t*>(&h2);
    lo = *reinterpret_cast<uint32_t*>(&l2);
}

#define STS128(addr, v) \
    asm volatile("st.shared.v4.b32 [%0], {%1,%2,%3,%4};" \
                 :: "r"(addr), "r"((v).x), "r"((v).y), "r"((v).z), "r"((v).w) \
                 : "memory")
#define STS32(addr, v) \
    asm volatile("st.shared.b32 [%0], %1;" :: "r"(addr), "r"(v) : "memory")

__device__ __forceinline__ void ldmx4(uint32_t* r, uint32_t addr) {
    asm volatile("ldmatrix.sync.aligned.m8n8.x4.shared.b16 {%0,%1,%2,%3}, [%4];"
        : "=r"(r[0]), "=r"(r[1]), "=r"(r[2]), "=r"(r[3]) : "r"(addr));
}

__device__ __forceinline__ void mma16816(float* d, const uint32_t* a,
                                         const uint32_t* b) {
    asm volatile(
        "mma.sync.aligned.m16n8k16.row.col.f32.bf16.bf16.f32 "
        "{%0,%1,%2,%3}, {%4,%5,%6,%7}, {%8,%9}, {%0,%1,%2,%3};"
        : "+f"(d[0]), "+f"(d[1]), "+f"(d[2]), "+f"(d[3])
        : "r"(a[0]), "r"(a[1]), "r"(a[2]), "r"(a[3]), "r"(b[0]), "r"(b[1]));
}

// smem byte offsets
#define OFF_AHI  0
#define OFF_ALO  16384
#define OFF_WF2  32768
#define OFF_WF3  49152
#define OFF_W1R  65536
#define OFF_B2V  65792
#define OFF_B3V  66048
#define OFF_W4V  66304
#define SMEM_TOTAL 66560

// D = Ahi@Bhi + Ahi@Blo + Alo@Bhi, A from swizzled smem via ldmatrix,
// B fragments pre-packed per-lane in wf (uint4 = {bhi0,bhi1,blo0,blo1}).
__device__ __forceinline__ void gemm_mma(
    uint32_t aHi, uint32_t aLo, const uint4* __restrict__ wf,
    const float* __restrict__ bias, int lane, int m0, float (&D)[2][8][4])
{
    int tig = lane & 3;
    uint32_t AH[2][4][4], AL[2][4][4];
    int Lmat = lane >> 3;
    #pragma unroll
    for (int mt = 0; mt < 2; mt++) {
        #pragma unroll
        for (int kt = 0; kt < 4; kt++) {
            int r = m0 + mt * 16 + (Lmat & 1) * 8 + (lane & 7);
            int chunk = kt * 2 + (Lmat >> 1);
            uint32_t off = (uint32_t)(r * 128 + ((chunk ^ (r & 7)) << 4));
            ldmx4(AH[mt][kt], aHi + off);
            ldmx4(AL[mt][kt], aLo + off);
        }
    }
    #pragma unroll
    for (int mt = 0; mt < 2; mt++) {
        #pragma unroll
        for (int nt = 0; nt < 8; nt++) {
            float b0 = bias[nt * 8 + tig * 2];
            float b1 = bias[nt * 8 + tig * 2 + 1];
            D[mt][nt][0] = b0; D[mt][nt][1] = b1;
            D[mt][nt][2] = b0; D[mt][nt][3] = b1;
        }
    }
    #pragma unroll
    for (int nt = 0; nt < 8; nt++) {
        uint4 w[4];
        #pragma unroll
        for (int kt = 0; kt < 4; kt++) w[kt] = wf[(nt * 4 + kt) * 32 + lane];
        #pragma unroll
        for (int kt = 0; kt < 4; kt++) {
            uint32_t bh[2] = { w[kt].x, w[kt].y };
            uint32_t bl[2] = { w[kt].z, w[kt].w };
            #pragma unroll
            for (int mt = 0; mt < 2; mt++) {
                mma16816(D[mt][nt], AH[mt][kt], bh);
                mma16816(D[mt][nt], AH[mt][kt], bl);
                mma16816(D[mt][nt], AL[mt][kt], bh);
            }
        }
    }
}

// ---------------------------- Kernel 2: edges -------------------------------
__global__ void __launch_bounds__(128, 2) edge_mma_kernel(
    const float* __restrict__ x,
    const int* __restrict__ src, const int* __restrict__ dst,
    const float* __restrict__ W1,
    const float* __restrict__ W2, const float* __restrict__ b2,
    const float* __restrict__ W3, const float* __restrict__ b3,
    const float* __restrict__ W4,
    float* __restrict__ out, int E)
{
    extern __shared__ char sm[];
    uint32_t smb = (uint32_t)__cvta_generic_to_shared(sm);
    int tid = threadIdx.x;
    int lane = tid & 31;
    int warp = tid >> 5;
    int m0 = warp * 32;
    int gid = lane >> 2, tig = lane & 3;

    // ---- prologue: pack W2/W3 per-lane mma fragments (hi/lo) + vectors ----
    {
        uint4* wf2 = (uint4*)(sm + OFF_WF2);
        uint4* wf3 = (uint4*)(sm + OFF_WF3);
        for (int idx = tid; idx < 1024; idx += 128) {
            int t = idx >> 5, l = idx & 31;
            int kt = t & 3, nt = t >> 2;
            int g = l >> 2, tg = l & 3;
            int k0 = kt * 16 + tg * 2;
            int n = nt * 8 + g;
            #pragma unroll
            for (int layer = 0; layer < 2; layer++) {
                const float* W = layer ? W3 : W2;
                float w00 = W[k0 * 64 + n],       w01 = W[(k0 + 1) * 64 + n];
                float w10 = W[(k0 + 8) * 64 + n], w11 = W[(k0 + 9) * 64 + n];
                uint4 v;
                split_pair(w00, w01, v.x, v.z);
                split_pair(w10, w11, v.y, v.w);
                (layer ? wf3 : wf2)[idx] = v;
            }
        }
        if (tid < 64) {
            ((float*)(sm + OFF_W1R))[tid] = W1[tid];
            ((float*)(sm + OFF_B2V))[tid] = b2[tid];
            ((float*)(sm + OFF_B3V))[tid] = b3[tid];
            ((float*)(sm + OFF_W4V))[tid] = W4[tid];
        }
    }
    __syncthreads();

    // ---- edge prep: one edge per thread = row tid of the 128-row tile ----
    int base = blockIdx.x * 128;
    int e = base + tid;
    bool valid = e < E;
    int s = 0, dn = 0;
    if (valid) { s = src[e]; dn = dst[e]; }
    float cx = x[s * 3 + 0] - x[dn * 3 + 0];
    float cy = x[s * 3 + 1] - x[dn * 3 + 1];
    float cz = x[s * 3 + 2] - x[dn * 3 + 2];
    float r = cx * cx + cy * cy + cz * cz;
    if (valid) out[e] = r;

    uint32_t aHi = smb + OFF_AHI, aLo = smb + OFF_ALO;

    // ---- layer 1: h1 -> smem (bf16 hi/lo, chunk-swizzled rows) ----
    {
        const float4* pa = (const float4*)(g_P + (size_t)s * 128);
        const float4* pb = (const float4*)(g_P + (size_t)dn * 128 + 64);
        const float4* w1q = (const float4*)(sm + OFF_W1R);
        uint32_t rowHi = aHi + (uint32_t)tid * 128;
        uint32_t rowLo = aLo + (uint32_t)tid * 128;
        uint32_t rsw = (uint32_t)(tid & 7);
        #pragma unroll
        for (int cq = 0; cq < 8; cq++) {
            float h[8];
            #pragma unroll
            for (int half = 0; half < 2; half++) {
                int q = 2 * cq + half;
                float4 a = pa[q], b = pb[q], w = w1q[q];
                h[4 * half + 0] = siluf(fmaf(r, w.x, a.x + b.x));
                h[4 * half + 1] = siluf(fmaf(r, w.y, a.y + b.y));
                h[4 * half + 2] = siluf(fmaf(r, w.z, a.z + b.z));
                h[4 * half + 3] = siluf(fmaf(r, w.w, a.w + b.w));
            }
            uint4 vhi, vlo;
            split_pair(h[0], h[1], vhi.x, vlo.x);
            split_pair(h[2], h[3], vhi.y, vlo.y);
            split_pair(h[4], h[5], vhi.z, vlo.z);
            split_pair(h[6], h[7], vhi.w, vlo.w);
            uint32_t csw = (uint32_t)((cq ^ rsw) * 16);
            STS128(rowHi + csw, vhi);
            STS128(rowLo + csw, vlo);
        }
    }
    __syncwarp();

    // ---- layer 2 GEMM + epilogue ----
    float D[2][8][4];
    gemm_mma(aHi, aLo, (const uint4*)(sm + OFF_WF2),
             (const float*)(sm + OFF_B2V), lane, m0, D);

    {
        float* fout = out + (size_t)4 * E;
        #pragma unroll
        for (int mt = 0; mt < 2; mt++) {
            int r0 = m0 + mt * 16 + gid;
            int r1 = r0 + 8;
            int e0 = base + r0, e1 = base + r1;
            #pragma unroll
            for (int nt = 0; nt < 8; nt++) {
                float v0 = siluf(D[mt][nt][0]);
                float v1 = siluf(D[mt][nt][1]);
                float v2 = siluf(D[mt][nt][2]);
                float v3 = siluf(D[mt][nt][3]);
                int col = nt * 8 + tig * 2;
                if (e0 < E)
                    *(float2*)(fout + (size_t)e0 * 64 + col) = make_float2(v0, v1);
                if (e1 < E)
                    *(float2*)(fout + (size_t)e1 * 64 + col) = make_float2(v2, v3);
                uint32_t off0 = (uint32_t)(r0 * 128 + ((nt ^ (r0 & 7)) << 4) + tig * 4);
                uint32_t off1 = (uint32_t)(r1 * 128 + ((nt ^ (r1 & 7)) << 4) + tig * 4);
                uint32_t hi01, lo01, hi23, lo23;
                split_pair(v0, v1, hi01, lo01);
                split_pair(v2, v3, hi23, lo23);
                STS32(aHi + off0, hi01); STS32(aLo + off0, lo01);
                STS32(aHi + off1, hi23); STS32(aLo + off1, lo23);
            }
        }
    }
    __syncwarp();

    // ---- layer 3 GEMM + epilogue ----
    gemm_mma(aHi, aLo, (const uint4*)(sm + OFF_WF3),
             (const float*)(sm + OFF_B3V), lane, m0, D);

    {
        const float* w4v = (const float*)(sm + OFF_W4V);
        float dv[2][2] = { {0.f, 0.f}, {0.f, 0.f} };
        #pragma unroll
        for (int mt = 0; mt < 2; mt++) {
            #pragma unroll
            for (int nt = 0; nt < 8; nt++) {
                int col = nt * 8 + tig * 2;
                float wa = w4v[col], wb = w4v[col + 1];
                dv[mt][0] = fmaf(siluf(D[mt][nt][0]), wa,
                            fmaf(siluf(D[mt][nt][1]), wb, dv[mt][0]));
                dv[mt][1] = fmaf(siluf(D[mt][nt][2]), wa,
                            fmaf(siluf(D[mt][nt][3]), wb, dv[mt][1]));
            }
        }
        #pragma unroll
        for (int mt = 0; mt < 2; mt++) {
            #pragma unroll
            for (int half = 0; half < 2; half++) {
                dv[mt][half] += __shfl_xor_sync(0xffffffffu, dv[mt][half], 1);
                dv[mt][half] += __shfl_xor_sync(0xffffffffu, dv[mt][half], 2);
            }
        }
        // lane tig takes row (mt=tig>>1, half=tig&1)
        float dsel = (tig == 0) ? dv[0][0] : (tig == 1) ? dv[0][1]
                   : (tig == 2) ? dv[1][0] : dv[1][1];
        int rw = (tig >> 1) * 16 + (tig & 1) * 8 + gid;   // row within warp
        float rr  = __shfl_sync(0xffffffffu, r,  rw);
        float cxx = __shfl_sync(0xffffffffu, cx, rw);
        float cyy = __shfl_sync(0xffffffffu, cy, rw);
        float czz = __shfl_sync(0xffffffffu, cz, rw);
        int ee = base + m0 + rw;
        float msc = __fdividef(tanhf(dsel), sqrtf(rr) + 1e-8f);
        if (ee < E) {
            float* outT = out + E;
            outT[3 * ee + 0] = cxx * msc;
            outT[3 * ee + 1] = cyy * msc;
            outT[3 * ee + 2] = czz * msc;
        }
    }
}

extern "C" void kernel_launch(void* const* d_in, const int* in_sizes, int n_in,
                              void* d_out, int out_size) {
    const float* x  = (const float*)d_in[0];
    const float* hh = (const float*)d_in[1];
    const int* src  = (const int*)d_in[2];
    const int* dst  = (const int*)d_in[3];
    const float* W1 = (const float*)d_in[4];
    const float* b1 = (const float*)d_in[5];
    const float* W2 = (const float*)d_in[6];
    const float* b2 = (const float*)d_in[7];
    const float* W3 = (const float*)d_in[8];
    const float* b3 = (const float*)d_in[9];
    const float* W4 = (const float*)d_in[10];
    int N = in_sizes[0] / 3;
    int E = in_sizes[2];
    float* out = (float*)d_out;

    cudaFuncSetAttribute(edge_mma_kernel,
                         cudaFuncAttributeMaxDynamicSharedMemorySize, SMEM_TOTAL);

    const int npb = 80;
    int pblocks = (N + npb - 1) / npb;
    precompute_P_kernel<<<pblocks, 256>>>(hh, W1, b1, N, npb);

    int eblocks = (E + 127) / 128;
    edge_mma_kernel<<<eblocks, 128, SMEM_TOTAL>>>(x, src, dst, W1, W2, b2,
                                                  W3, b3, W4, out, E);
    (void)n_in; (void)out_size;
}

// round 4
// speedup vs baseline: 2.1925x; 1.3312x over previous
#include <cuda_runtime.h>
#include <cuda_bf16.h>
#include <math.h>
#include <stdint.h>

// ---------------------------------------------------------------------------
// EGNN edge message via warp-level HMMA (mma.sync bf16, hi/lo split x3).
//   Kernel 1: P[n] = [ hh[n]@W1a + b1 | hh[n]@W1b ],  g_Xp[n] = padded x
//   Kernel 2 (per 128-edge block, 4 warps x 32 rows):
//     h1 = silu(Pa[s]+Pb[d]+r*W1row0)  (coalesced cooperative gather)
//     h2 = silu(h1@W2+b2)  mma.sync, A via ldmatrix     (edge_feature)
//     h3 = silu(h2@W3+b3)  mma.sync, A built IN REGISTERS from h2 fragments
//     sc = tanh(h3.W4); trans = cd*sc/(sqrt(r)+eps)
// Output: [ radial (E) | trans (3E) | edge_feature (64E) ]
// ---------------------------------------------------------------------------

#define N_MAX_NODES 50048
__device__ float  g_P[(size_t)N_MAX_NODES * 128];
__device__ float4 g_Xp[N_MAX_NODES];

__device__ __forceinline__ float siluf(float v) {
    return __fdividef(v, 1.0f + __expf(-v));
}

// ---------------- Kernel 1: per-node projection precompute -----------------
__global__ void __launch_bounds__(256) precompute_P_kernel(
    const float* __restrict__ x,
    const float* __restrict__ hh, const float* __restrict__ W1,
    const float* __restrict__ b1, int n_nodes, int nodes_per_block)
{
    __shared__ float W1s[129 * 64];
    __shared__ float b1s[64];
    int tid = threadIdx.x;
    for (int i = tid; i < 129 * 64; i += 256) W1s[i] = W1[i];
    if (tid < 64) b1s[tid] = b1[tid];
    __syncthreads();

    int lane = tid & 31, warp = tid >> 5;
    for (int nn = warp; nn < nodes_per_block; nn += 8) {
        int n = blockIdx.x * nodes_per_block + nn;
        if (n >= n_nodes) return;
        if (lane == 0)
            g_Xp[n] = make_float4(x[3 * n], x[3 * n + 1], x[3 * n + 2], 0.f);
        float hlo = hh[(size_t)n * 64 + lane];
        float hhi = hh[(size_t)n * 64 + 32 + lane];
        float a0 = b1s[lane], a1 = b1s[lane + 32];
        float c0 = 0.f, c1 = 0.f;
        #pragma unroll
        for (int k = 0; k < 64; k++) {
            float hk = __shfl_sync(0xffffffffu, (k < 32) ? hlo : hhi, k & 31);
            a0 = fmaf(hk, W1s[(1 + k) * 64 + lane],        a0);
            a1 = fmaf(hk, W1s[(1 + k) * 64 + 32 + lane],   a1);
            c0 = fmaf(hk, W1s[(65 + k) * 64 + lane],       c0);
            c1 = fmaf(hk, W1s[(65 + k) * 64 + 32 + lane],  c1);
        }
        float* Pr = g_P + (size_t)n * 128;
        Pr[lane] = a0; Pr[lane + 32] = a1;
        Pr[64 + lane] = c0; Pr[96 + lane] = c1;
    }
}

// ------------------------------ helpers ------------------------------------
__device__ __forceinline__ void split_pair(float a, float b,
                                           uint32_t& hi, uint32_t& lo) {
    __nv_bfloat162 h2 = __floats2bfloat162_rn(a, b);
    float ra = a - __bfloat162float(h2.x);
    float rb = b - __bfloat162float(h2.y);
    __nv_bfloat162 l2 = __floats2bfloat162_rn(ra, rb);
    hi = *reinterpret_cast<uint32_t*>(&h2);
    lo = *reinterpret_cast<uint32_t*>(&l2);
}

#define STS64(addr, v0, v1) \
    asm volatile("st.shared.v2.b32 [%0], {%1,%2};" \
                 :: "r"(addr), "r"(v0), "r"(v1) : "memory")

__device__ __forceinline__ void ldmx4(uint32_t* r, uint32_t addr) {
    asm volatile("ldmatrix.sync.aligned.m8n8.x4.shared.b16 {%0,%1,%2,%3}, [%4];"
        : "=r"(r[0]), "=r"(r[1]), "=r"(r[2]), "=r"(r[3]) : "r"(addr));
}

__device__ __forceinline__ void mma16816(float* d, const uint32_t* a,
                                         const uint32_t* b) {
    asm volatile(
        "mma.sync.aligned.m16n8k16.row.col.f32.bf16.bf16.f32 "
        "{%0,%1,%2,%3}, {%4,%5,%6,%7}, {%8,%9}, {%0,%1,%2,%3};"
        : "+f"(d[0]), "+f"(d[1]), "+f"(d[2]), "+f"(d[3])
        : "r"(a[0]), "r"(a[1]), "r"(a[2]), "r"(a[3]), "r"(b[0]), "r"(b[1]));
}

// smem byte offsets
#define OFF_AHI  0
#define OFF_ALO  16384
#define OFF_WF2  32768
#define OFF_WF3  49152
#define OFF_W1R  65536
#define OFF_B2V  65792
#define OFF_B3V  66048
#define OFF_W4V  66304
#define SMEM_TOTAL 66560

// ---------------------------- Kernel 2: edges -------------------------------
__global__ void __launch_bounds__(128, 3) edge_mma_kernel(
    const int* __restrict__ src, const int* __restrict__ dst,
    const float* __restrict__ W1,
    const float* __restrict__ W2, const float* __restrict__ b2,
    const float* __restrict__ W3, const float* __restrict__ b3,
    const float* __restrict__ W4,
    float* __restrict__ out, int E)
{
    extern __shared__ char sm[];
    uint32_t smb = (uint32_t)__cvta_generic_to_shared(sm);
    int tid = threadIdx.x;
    int lane = tid & 31;
    int warp = tid >> 5;
    int m0 = warp * 32;
    int gid = lane >> 2, tig = lane & 3;

    // ---- prologue: pack W2/W3 per-lane mma fragments (hi/lo) + vectors ----
    {
        uint4* wf2 = (uint4*)(sm + OFF_WF2);
        uint4* wf3 = (uint4*)(sm + OFF_WF3);
        for (int idx = tid; idx < 1024; idx += 128) {
            int t = idx >> 5, l = idx & 31;
            int kt = t & 3, nt = t >> 2;
            int g = l >> 2, tg = l & 3;
            int k0 = kt * 16 + tg * 2;
            int n = nt * 8 + g;
            #pragma unroll
            for (int layer = 0; layer < 2; layer++) {
                const float* W = layer ? W3 : W2;
                float w00 = W[k0 * 64 + n],       w01 = W[(k0 + 1) * 64 + n];
                float w10 = W[(k0 + 8) * 64 + n], w11 = W[(k0 + 9) * 64 + n];
                uint4 v;
                split_pair(w00, w01, v.x, v.z);
                split_pair(w10, w11, v.y, v.w);
                (layer ? wf3 : wf2)[idx] = v;
            }
        }
        if (tid < 64) {
            ((float*)(sm + OFF_W1R))[tid] = W1[tid];
            ((float*)(sm + OFF_B2V))[tid] = b2[tid];
            ((float*)(sm + OFF_B3V))[tid] = b3[tid];
            ((float*)(sm + OFF_W4V))[tid] = W4[tid];
        }
    }
    __syncthreads();

    // ---- edge prep: one edge per thread = row (m0+lane) of the tile ----
    int base = blockIdx.x * 128;
    int e = base + m0 + lane;            // this warp's own rows
    bool valid = e < E;
    int s = 0, dn = 0;
    if (valid) { s = src[e]; dn = dst[e]; }
    float4 xs = g_Xp[s], xd = g_Xp[dn];
    float cx = xs.x - xd.x, cy = xs.y - xd.y, cz = xs.z - xd.z;
    float r = cx * cx + cy * cy + cz * cz;
    if (valid) out[e] = r;

    uint32_t aHi = smb + OFF_AHI, aLo = smb + OFF_ALO;

    // ---- layer 1: cooperative coalesced gather + silu -> smem A tile ----
    // 4 groups of 8 lanes; group handles one edge per j, lanes cover 128B.
    {
        const float4* w1q = (const float4*)(sm + OFF_W1R);
        int g = lane >> 3, c = lane & 7;
        const char* Pb = (const char*)g_P;
        #pragma unroll
        for (int j = 0; j < 8; j++) {
            int sl = j * 4 + g;
            int sE = __shfl_sync(0xffffffffu, s,  sl);
            int dE = __shfl_sync(0xffffffffu, dn, sl);
            float rE = __shfl_sync(0xffffffffu, r, sl);
            int row = m0 + j * 4 + g;
            uint32_t rowHi = aHi + (uint32_t)row * 128;
            uint32_t rowLo = aLo + (uint32_t)row * 128;
            int rx = row & 7;
            #pragma unroll
            for (int half = 0; half < 2; half++) {
                int q = half * 8 + c;
                float4 a = *(const float4*)(Pb + (size_t)sE * 512 + half * 128 + c * 16);
                float4 b = *(const float4*)(Pb + (size_t)dE * 512 + 256 + half * 128 + c * 16);
                float4 w = w1q[q];
                float h0 = siluf(fmaf(rE, w.x, a.x + b.x));
                float h1 = siluf(fmaf(rE, w.y, a.y + b.y));
                float h2 = siluf(fmaf(rE, w.z, a.z + b.z));
                float h3 = siluf(fmaf(rE, w.w, a.w + b.w));
                uint32_t hi0, lo0, hi1, lo1;
                split_pair(h0, h1, hi0, lo0);
                split_pair(h2, h3, hi1, lo1);
                uint32_t off = (uint32_t)((((q >> 1) ^ rx) << 4) + (q & 1) * 8);
                STS64(rowHi + off, hi0, hi1);
                STS64(rowLo + off, lo0, lo1);
            }
        }
    }
    __syncwarp();

    // ---- layer 2 GEMM: A via ldmatrix, W frags from smem ----
    float D[2][8][4];
    {
        uint32_t AH[2][4][4], AL[2][4][4];
        int Lmat = lane >> 3;
        #pragma unroll
        for (int mt = 0; mt < 2; mt++) {
            #pragma unroll
            for (int kt = 0; kt < 4; kt++) {
                int rr = m0 + mt * 16 + (Lmat & 1) * 8 + (lane & 7);
                int chunk = kt * 2 + (Lmat >> 1);
                uint32_t off = (uint32_t)(rr * 128 + ((chunk ^ (rr & 7)) << 4));
                ldmx4(AH[mt][kt], aHi + off);
                ldmx4(AL[mt][kt], aLo + off);
            }
        }
        const float* b2v = (const float*)(sm + OFF_B2V);
        #pragma unroll
        for (int mt = 0; mt < 2; mt++)
            #pragma unroll
            for (int nt = 0; nt < 8; nt++) {
                float b0 = b2v[nt * 8 + tig * 2];
                float b1 = b2v[nt * 8 + tig * 2 + 1];
                D[mt][nt][0] = b0; D[mt][nt][1] = b1;
                D[mt][nt][2] = b0; D[mt][nt][3] = b1;
            }
        const uint4* wf = (const uint4*)(sm + OFF_WF2);
        #pragma unroll
        for (int nt = 0; nt < 8; nt++) {
            uint4 w[4];
            #pragma unroll
            for (int kt = 0; kt < 4; kt++) w[kt] = wf[(nt * 4 + kt) * 32 + lane];
            #pragma unroll
            for (int kt = 0; kt < 4; kt++) {
                uint32_t bh[2] = { w[kt].x, w[kt].y };
                uint32_t bl[2] = { w[kt].z, w[kt].w };
                #pragma unroll
                for (int mt = 0; mt < 2; mt++) {
                    mma16816(D[mt][nt], AH[mt][kt], bh);
                    mma16816(D[mt][nt], AH[mt][kt], bl);
                    mma16816(D[mt][nt], AL[mt][kt], bh);
                }
            }
        }
    }

    // ---- layer 2 epilogue: h2 = silu(D+b2); write features; build A3 regs ----
    uint32_t A3H[2][4][4], A3L[2][4][4];
    {
        float* fout = out + (size_t)4 * E;
        #pragma unroll
        for (int mt = 0; mt < 2; mt++) {
            int r0 = m0 + mt * 16 + gid;
            int r1 = r0 + 8;
            int e0 = base + r0, e1 = base + r1;
            #pragma unroll
            for (int nt = 0; nt < 8; nt++) {
                float v0 = siluf(D[mt][nt][0]);
                float v1 = siluf(D[mt][nt][1]);
                float v2 = siluf(D[mt][nt][2]);
                float v3 = siluf(D[mt][nt][3]);
                int col = nt * 8 + tig * 2;
                if (e0 < E)
                    *(float2*)(fout + (size_t)e0 * 64 + col) = make_float2(v0, v1);
                if (e1 < E)
                    *(float2*)(fout + (size_t)e1 * 64 + col) = make_float2(v2, v3);
                // D fragment layout == A fragment layout for next GEMM:
                int kt = nt >> 1, hi = (nt & 1) * 2;
                split_pair(v0, v1, A3H[mt][kt][hi],     A3L[mt][kt][hi]);
                split_pair(v2, v3, A3H[mt][kt][hi + 1], A3L[mt][kt][hi + 1]);
            }
        }
    }

    // ---- layer 3 GEMM: A from registers, W frags from smem ----
    {
        const float* b3v = (const float*)(sm + OFF_B3V);
        #pragma unroll
        for (int mt = 0; mt < 2; mt++)
            #pragma unroll
            for (int nt = 0; nt < 8; nt++) {
                float b0 = b3v[nt * 8 + tig * 2];
                float b1 = b3v[nt * 8 + tig * 2 + 1];
                D[mt][nt][0] = b0; D[mt][nt][1] = b1;
                D[mt][nt][2] = b0; D[mt][nt][3] = b1;
            }
        const uint4* wf = (const uint4*)(sm + OFF_WF3);
        #pragma unroll
        for (int nt = 0; nt < 8; nt++) {
            uint4 w[4];
            #pragma unroll
            for (int kt = 0; kt < 4; kt++) w[kt] = wf[(nt * 4 + kt) * 32 + lane];
            #pragma unroll
            for (int kt = 0; kt < 4; kt++) {
                uint32_t bh[2] = { w[kt].x, w[kt].y };
                uint32_t bl[2] = { w[kt].z, w[kt].w };
                #pragma unroll
                for (int mt = 0; mt < 2; mt++) {
                    mma16816(D[mt][nt], A3H[mt][kt], bh);
                    mma16816(D[mt][nt], A3H[mt][kt], bl);
                    mma16816(D[mt][nt], A3L[mt][kt], bh);
                }
            }
        }
    }

    // ---- layer 3 epilogue: sc = tanh(silu(D+b3).W4); trans ----
    {
        const float* w4v = (const float*)(sm + OFF_W4V);
        float dv[2][2] = { {0.f, 0.f}, {0.f, 0.f} };
        #pragma unroll
        for (int mt = 0; mt < 2; mt++) {
            #pragma unroll
            for (int nt = 0; nt < 8; nt++) {
                int col = nt * 8 + tig * 2;
                float wa = w4v[col], wb = w4v[col + 1];
                dv[mt][0] = fmaf(siluf(D[mt][nt][0]), wa,
                            fmaf(siluf(D[mt][nt][1]), wb, dv[mt][0]));
                dv[mt][1] = fmaf(siluf(D[mt][nt][2]), wa,
                            fmaf(siluf(D[mt][nt][3]), wb, dv[mt][1]));
            }
        }
        #pragma unroll
        for (int mt = 0; mt < 2; mt++) {
            #pragma unroll
            for (int half = 0; half < 2; half++) {
                dv[mt][half] += __shfl_xor_sync(0xffffffffu, dv[mt][half], 1);
                dv[mt][half] += __shfl_xor_sync(0xffffffffu, dv[mt][half], 2);
            }
        }
        float dsel = (tig == 0) ? dv[0][0] : (tig == 1) ? dv[0][1]
                   : (tig == 2) ? dv[1][0] : dv[1][1];
        int rw = (tig >> 1) * 16 + (tig & 1) * 8 + gid;
        float rr  = __shfl_sync(0xffffffffu, r,  rw);
        float cxx = __shfl_sync(0xffffffffu, cx, rw);
        float cyy = __shfl_sync(0xffffffffu, cy, rw);
        float czz = __shfl_sync(0xffffffffu, cz, rw);
        int ee = base + m0 + rw;
        float msc = __fdividef(tanhf(dsel), sqrtf(rr) + 1e-8f);
        if (ee < E) {
            float* outT = out + E;
            outT[3 * ee + 0] = cxx * msc;
            outT[3 * ee + 1] = cyy * msc;
            outT[3 * ee + 2] = czz * msc;
        }
    }
}

extern "C" void kernel_launch(void* const* d_in, const int* in_sizes, int n_in,
                              void* d_out, int out_size) {
    const float* x  = (const float*)d_in[0];
    const float* hh = (const float*)d_in[1];
    const int* src  = (const int*)d_in[2];
    const int* dst  = (const int*)d_in[3];
    const float* W1 = (const float*)d_in[4];
    const float* b1 = (const float*)d_in[5];
    const float* W2 = (const float*)d_in[6];
    const float* b2 = (const float*)d_in[7];
    const float* W3 = (const float*)d_in[8];
    const float* b3 = (const float*)d_in[9];
    const float* W4 = (const float*)d_in[10];
    int N = in_sizes[0] / 3;
    int E = in_sizes[2];
    float* out = (float*)d_out;

    cudaFuncSetAttribute(edge_mma_kernel,
                         cudaFuncAttributeMaxDynamicSharedMemorySize, SMEM_TOTAL);

    const int npb = 80;
    int pblocks = (N + npb - 1) / npb;
    precompute_P_kernel<<<pblocks, 256>>>(x, hh, W1, b1, N, npb);

    int eblocks = (E + 127) / 128;
    edge_mma_kernel<<<eblocks, 128, SMEM_TOTAL>>>(src, dst, W1, W2, b2,
                                                  W3, b3, W4, out, E);
    (void)n_in; (void)out_size;
}